// round 1
// baseline (speedup 1.0000x reference)
#include <cuda_runtime.h>
#include <cstdint>

#define B_      2
#define CIN     256
#define Hdim    128
#define Wdim    128
#define KQ      128
#define HW      16384
#define NTOT    21504   // 16384 + 4096 + 1024
#define SCALE   0.08838834764831845f  // 128^-0.5

// ---------------- device scratch (static, no runtime alloc) ----------------
__device__ float g_wT [CIN * 9 * KQ];          // conv weights: [c][tap][k]
__device__ float g_kwT[KQ * KQ];               // key_w^T: [c][k]
__device__ float g_qwT[KQ * KQ];               // query_w^T: [c][k]
__device__ float g_x   [B_ * HW * KQ];         // conv out: [b*m][k]
__device__ float g_keys[B_ * HW * KQ];         // [b*m][k]
__device__ float g_qrs [B_ * HW * KQ];
__device__ float g_k2[B_ * 4096 * KQ], g_q2[B_ * 4096 * KQ];
__device__ float g_k4[B_ * 1024 * KQ], g_q4[B_ * 1024 * KQ];

// ---------------- weight transposes ----------------
__global__ __launch_bounds__(256) void prep_w(const float* __restrict__ conv_w,
                                              const float* __restrict__ key_w,
                                              const float* __restrict__ query_w) {
    int i = blockIdx.x * 256 + threadIdx.x;
    if (i < CIN * 9 * KQ) {
        int k = i % KQ;
        int t = (i / KQ) % 9;
        int c = i / (KQ * 9);
        g_wT[i] = conv_w[(k * CIN + c) * 9 + t];
    }
    if (i < KQ * KQ) {
        int k = i % KQ, c = i / KQ;
        g_kwT[i] = key_w[k * KQ + c];
        g_qwT[i] = query_w[k * KQ + c];
    }
}

// ---------------- 3x3 SAME conv (zero pad), fp32 tiled ----------------
// CTA: 2 rows x 32 cols spatial tile, all 128 out channels.
// thread: 8 spatial (one row, 8 consecutive cols) x 4 channels.
__global__ __launch_bounds__(256) void conv3x3(const float* __restrict__ feats,
                                               const float* __restrict__ conv_b) {
    __shared__ float s_in[8 * 4 * 34];   // [cc][y(4)][x(34)]
    __shared__ float s_w [8 * 9 * 128];  // [cc][tap][k]

    const int b   = blockIdx.z;
    const int ty0 = blockIdx.y * 2;
    const int tx0 = blockIdx.x * 32;
    const int tid = threadIdx.x;
    const int grp = tid >> 5;            // 0..7
    const int tr  = grp >> 2;            // row within tile: 0/1
    const int tcb = (grp & 3) * 8;       // col base within tile
    const int kb  = (tid & 31) * 4;      // out-channel base

    float acc[8][4];
    #pragma unroll
    for (int i = 0; i < 8; i++)
        #pragma unroll
        for (int j = 0; j < 4; j++) acc[i][j] = conv_b[kb + j];

    for (int c0 = 0; c0 < CIN; c0 += 8) {
        __syncthreads();
        // input tile: 8 ch x 4 rows x 34 cols, zero-padded at borders
        for (int idx = tid; idx < 8 * 136; idx += 256) {
            int cc  = idx / 136;
            int rem = idx % 136;
            int y = rem / 34, x = rem % 34;
            int gy = ty0 + y - 1, gx = tx0 + x - 1;
            float v = 0.f;
            if (gy >= 0 && gy < Hdim && gx >= 0 && gx < Wdim)
                v = feats[(((size_t)b * CIN + c0 + cc) * Hdim + gy) * Wdim + gx];
            s_in[idx] = v;
        }
        // weights: contiguous copy of 9216 floats from g_wT
        {
            const float4* src = (const float4*)(g_wT + (size_t)c0 * 9 * KQ);
            float4* dst = (float4*)s_w;
            for (int idx = tid; idx < 2304; idx += 256) dst[idx] = src[idx];
        }
        __syncthreads();

        #pragma unroll
        for (int cc = 0; cc < 8; cc++) {
            #pragma unroll
            for (int dy = 0; dy < 3; dy++) {
                float r[10];
                #pragma unroll
                for (int ii = 0; ii < 10; ii++)
                    r[ii] = s_in[cc * 136 + (tr + dy) * 34 + tcb + ii];
                #pragma unroll
                for (int dx = 0; dx < 3; dx++) {
                    float4 wv = *(const float4*)&s_w[cc * 1152 + (dy * 3 + dx) * 128 + kb];
                    #pragma unroll
                    for (int i = 0; i < 8; i++) {
                        float a = r[i + dx];
                        acc[i][0] += a * wv.x;
                        acc[i][1] += a * wv.y;
                        acc[i][2] += a * wv.z;
                        acc[i][3] += a * wv.w;
                    }
                }
            }
        }
    }

    #pragma unroll
    for (int i = 0; i < 8; i++) {
        int m = (ty0 + tr) * Wdim + tx0 + tcb + i;
        float4 v = make_float4(acc[i][0], acc[i][1], acc[i][2], acc[i][3]);
        *(float4*)&g_x[((size_t)b * HW + m) * KQ + kb] = v;
    }
}

// ---------------- key/query projections: out[m][k] = sum_c x[m][c]*wT[c][k]+b[k]
__global__ __launch_bounds__(256) void proj(const float* __restrict__ key_b,
                                            const float* __restrict__ query_b) {
    __shared__ float s_a[32][65];     // [c][m] padded
    __shared__ float s_b[32 * 128];   // [c][k]

    const int which = blockIdx.y;     // 0: keys, 1: queries
    const float* wT   = which ? g_qwT : g_kwT;
    const float* bias = which ? query_b : key_b;
    float* out        = which ? g_qrs : g_keys;

    const size_t mbase = (size_t)blockIdx.x * 64;   // over B_*HW
    const int tid = threadIdx.x;
    const int grp = tid >> 5;
    const int kbb = (tid & 31) * 4;

    float acc[8][4];
    #pragma unroll
    for (int i = 0; i < 8; i++)
        #pragma unroll
        for (int j = 0; j < 4; j++) acc[i][j] = bias[kbb + j];

    for (int c0 = 0; c0 < KQ; c0 += 32) {
        __syncthreads();
        {   // A tile: 64 m x 32 c (transpose into [c][m])
            int m = tid >> 3;          // 0..31
            int l = tid & 7;           // c-group (4 floats)
            #pragma unroll
            for (int half = 0; half < 2; half++) {
                int mm = m + half * 32;
                float4 v = *(const float4*)&g_x[(mbase + mm) * KQ + c0 + l * 4];
                s_a[l * 4 + 0][mm] = v.x;
                s_a[l * 4 + 1][mm] = v.y;
                s_a[l * 4 + 2][mm] = v.z;
                s_a[l * 4 + 3][mm] = v.w;
            }
        }
        {   // B tile: 32 c x 128 k, contiguous from wT
            const float4* src = (const float4*)(wT + (size_t)c0 * KQ);
            float4* dst = (float4*)s_b;
            for (int idx = tid; idx < 1024; idx += 256) dst[idx] = src[idx];
        }
        __syncthreads();

        #pragma unroll
        for (int cc = 0; cc < 32; cc++) {
            float4 wv = *(const float4*)&s_b[cc * 128 + kbb];
            #pragma unroll
            for (int i = 0; i < 8; i++) {
                float a = s_a[cc][grp * 8 + i];
                acc[i][0] += a * wv.x;
                acc[i][1] += a * wv.y;
                acc[i][2] += a * wv.z;
                acc[i][3] += a * wv.w;
            }
        }
    }

    #pragma unroll
    for (int i = 0; i < 8; i++) {
        float4 v = make_float4(acc[i][0], acc[i][1], acc[i][2], acc[i][3]);
        *(float4*)&out[(mbase + grp * 8 + i) * KQ + kbb] = v;
    }
}

// ---------------- avg pool s x s, [b][m][c] -> [b][n][c] ----------------
__global__ __launch_bounds__(256) void pool_kernel(int s) {
    const float* in = blockIdx.z ? g_qrs : g_keys;
    float* out;
    const int hp = Hdim / s;
    const int n  = hp * hp;
    if (s == 2) out = blockIdx.z ? g_q2 : g_k2;
    else        out = blockIdx.z ? g_q4 : g_k4;

    int idx = blockIdx.x * 256 + threadIdx.x;   // float4 units
    if (idx >= B_ * n * 32) return;
    int c4 = idx & 31;
    int nn = (idx >> 5) % n;
    int b  = idx / (n * 32);
    int y = nn / hp, x = nn % hp;

    float4 acc = make_float4(0.f, 0.f, 0.f, 0.f);
    for (int ry = 0; ry < s; ry++)
        for (int rx = 0; rx < s; rx++) {
            int m = (y * s + ry) * Wdim + x * s + rx;
            float4 v = *(const float4*)&in[((size_t)b * HW + m) * KQ + c4 * 4];
            acc.x += v.x; acc.y += v.y; acc.z += v.z; acc.w += v.w;
        }
    float inv = 1.f / (float)(s * s);
    acc.x *= inv; acc.y *= inv; acc.z *= inv; acc.w *= inv;
    *(float4*)&out[((size_t)b * n + nn) * KQ + c4 * 4] = acc;
}

// ---------------- logits: warp per position, lane splits channels ----------------
__global__ __launch_bounds__(256) void logits_kernel(const int* __restrict__ inds,
                                                     float* __restrict__ out,
                                                     int n, int n_off, int lvl) {
    const float* q;
    const float* k;
    if (lvl == 0)      { q = g_qrs; k = g_keys; }
    else if (lvl == 1) { q = g_q2;  k = g_k2;  }
    else               { q = g_q4;  k = g_k4;  }

    const int warp = threadIdx.x >> 5;
    const int lane = threadIdx.x & 31;
    const int nn = blockIdx.x * 8 + warp;
    const int b  = blockIdx.z;
    if (nn >= n) return;

    float4 qv = *(const float4*)&q[((size_t)b * n + nn) * KQ + lane * 4];
    const int* ip = inds + ((size_t)b * n + nn) * 32;

    float myval = 0.f;
    #pragma unroll 4
    for (int s = 0; s < 32; s++) {
        int ind = ip[s];
        float4 kv = *(const float4*)&k[((size_t)b * n + ind) * KQ + lane * 4];
        float p = qv.x * kv.x + qv.y * kv.y + qv.z * kv.z + qv.w * kv.w;
        p += __shfl_xor_sync(0xffffffffu, p, 1);
        p += __shfl_xor_sync(0xffffffffu, p, 2);
        p += __shfl_xor_sync(0xffffffffu, p, 4);
        p += __shfl_xor_sync(0xffffffffu, p, 8);
        p += __shfl_xor_sync(0xffffffffu, p, 16);
        if (lane == s) myval = p * SCALE;
    }
    out[((size_t)b * NTOT + n_off + nn) * 32 + lane] = myval;
}

// ---------------- launch ----------------
extern "C" void kernel_launch(void* const* d_in, const int* in_sizes, int n_in,
                              void* d_out, int out_size) {
    const float* feats   = (const float*)d_in[0];
    const float* conv_w  = (const float*)d_in[1];
    const float* conv_b  = (const float*)d_in[2];
    const float* key_w   = (const float*)d_in[3];
    const float* key_b   = (const float*)d_in[4];
    const float* query_w = (const float*)d_in[5];
    const float* query_b = (const float*)d_in[6];
    const int* si2 = (const int*)d_in[7];
    const int* si3 = (const int*)d_in[8];
    const int* si4 = (const int*)d_in[9];
    float* out = (float*)d_out;

    prep_w<<<1152, 256>>>(conv_w, key_w, query_w);
    conv3x3<<<dim3(Wdim / 32, Hdim / 2, B_), 256>>>(feats, conv_b);
    proj<<<dim3((B_ * HW) / 64, 2, 1), 256>>>(key_b, query_b);
    pool_kernel<<<dim3((B_ * 4096 * 32 + 255) / 256, 1, 2), 256>>>(2);
    pool_kernel<<<dim3((B_ * 1024 * 32 + 255) / 256, 1, 2), 256>>>(4);
    logits_kernel<<<dim3(16384 / 8, 1, B_), 256>>>(si2, out, 16384, 0, 0);
    logits_kernel<<<dim3(4096 / 8, 1, B_), 256>>>(si3, out, 4096, 16384, 1);
    logits_kernel<<<dim3(1024 / 8, 1, B_), 256>>>(si4, out, 1024, 20480, 2);
}